// round 1
// baseline (speedup 1.0000x reference)
#include <cuda_runtime.h>
#include <math.h>

#define HID   128
#define HEADS 4
#define HDIM  32
#define NMAX  50176
#define EMAX  800000

// ---------------- scratch (device globals; no allocation allowed) ----------
__device__ float g_q[NMAX * HID];
__device__ float g_k[NMAX * HID];
__device__ float g_v[NMAX * HID];
__device__ float g_agg[NMAX * HID];
__device__ float g_expsum[NMAX * HEADS];
__device__ float g_w[EMAX * HEADS];

// ---------------- zero scratch --------------------------------------------
__global__ void zero_kernel(int n) {
    int i = blockIdx.x * blockDim.x + threadIdx.x;
    if (i < n * HID) g_agg[i] = 0.f;
    if (i < n * HEADS) g_expsum[i] = 0.f;
}

// ---------------- fused h_combined + QKV projections ----------------------
// out[m][c] = sum_k (h[m][k] + frac[m]·We[k] + be[k]) * W[c][k] + bias[c]
// grid: ((n+63)/64, 6) ; 64-row x 64-col tiles over 384 output cols (q|k|v)
__global__ void qkv_gemm(const float* __restrict__ h,
                         const float* __restrict__ frac,
                         const float* __restrict__ We,
                         const float* __restrict__ be,
                         const float* __restrict__ Wq, const float* __restrict__ bq,
                         const float* __restrict__ Wk, const float* __restrict__ bk,
                         const float* __restrict__ Wv, const float* __restrict__ bv,
                         int n) {
    __shared__ __align__(16) float As[16][68];
    __shared__ __align__(16) float Bs[16][68];

    int m0 = blockIdx.x * 64;
    int c0 = blockIdx.y * 64;           // 0..320 within 384
    const float* W;
    const float* bias;
    float* outbuf;
    if (c0 < 128)      { W = Wq; bias = bq; outbuf = g_q; }
    else if (c0 < 256) { W = Wk; bias = bk; outbuf = g_k; }
    else               { W = Wv; bias = bv; outbuf = g_v; }
    int cl0 = c0 & 127;

    int tid = threadIdx.y * 16 + threadIdx.x;
    int lk = tid & 15;      // k within chunk
    int lr = tid >> 4;      // row/col group

    float acc[4][4];
#pragma unroll
    for (int i = 0; i < 4; i++)
#pragma unroll
        for (int j = 0; j < 4; j++) acc[i][j] = 0.f;

    for (int kk = 0; kk < HID; kk += 16) {
        int kc = kk + lk;
        // load X tile (with fused frac embedding), transposed: As[k][m]
#pragma unroll
        for (int rr = 0; rr < 4; rr++) {
            int m = m0 + lr + rr * 16;
            float x = 0.f;
            if (m < n) {
                x = h[m * HID + kc]
                    + frac[m * 3 + 0] * We[kc * 3 + 0]
                    + frac[m * 3 + 1] * We[kc * 3 + 1]
                    + frac[m * 3 + 2] * We[kc * 3 + 2]
                    + be[kc];
            }
            As[lk][lr + rr * 16] = x;
        }
        // load W^T tile: Bs[k][c] = W[(cl0+c)*HID + kc]
#pragma unroll
        for (int nn = 0; nn < 4; nn++) {
            int cc = lr + nn * 16;
            Bs[lk][cc] = W[(cl0 + cc) * HID + kc];
        }
        __syncthreads();
#pragma unroll
        for (int k = 0; k < 16; k++) {
            float a[4], b[4];
            *(float4*)a = *(const float4*)&As[k][threadIdx.y * 4];
            *(float4*)b = *(const float4*)&Bs[k][threadIdx.x * 4];
#pragma unroll
            for (int i = 0; i < 4; i++)
#pragma unroll
                for (int j = 0; j < 4; j++) acc[i][j] += a[i] * b[j];
        }
        __syncthreads();
    }
#pragma unroll
    for (int i = 0; i < 4; i++) {
        int m = m0 + threadIdx.y * 4 + i;
        if (m >= n) continue;
#pragma unroll
        for (int j = 0; j < 4; j++) {
            int c = cl0 + threadIdx.x * 4 + j;
            outbuf[m * HID + c] = acc[i][j] + bias[c];
        }
    }
}

// ---------------- per-edge scores + gate + exp ----------------------------
// one warp per edge; no segment-max needed (scores are O(1), exp-safe; the
// softmax ratio is identical without the shift)
__global__ void edge_score(const int* __restrict__ ei,
                           const float* __restrict__ dist,
                           const float* __restrict__ Wg1, const float* __restrict__ bg1,
                           const float* __restrict__ Wg2, const float* __restrict__ bg2,
                           int E) {
    int warp = (blockIdx.x * blockDim.x + threadIdx.x) >> 5;
    int lane = threadIdx.x & 31;
    if (warp >= E) return;
    int row = ei[warp];
    int col = ei[E + warp];

    float4 qv = *(const float4*)&g_q[row * HID + lane * 4];
    float4 kv = *(const float4*)&g_k[col * HID + lane * 4];
    float p = qv.x * kv.x + qv.y * kv.y + qv.z * kv.z + qv.w * kv.w;
    // reduce within 8-lane groups (one head per group)
    p += __shfl_xor_sync(0xFFFFFFFFu, p, 1);
    p += __shfl_xor_sync(0xFFFFFFFFu, p, 2);
    p += __shfl_xor_sync(0xFFFFFFFFu, p, 4);

    // gate MLP: 1 -> 32 (silu) -> 1 (sigmoid); lane l handles hidden unit l
    float d = dist[warp];
    float t = fmaf(d, Wg1[lane], bg1[lane]);
    float hsi = t / (1.f + expf(-t));        // silu
    float gp = hsi * Wg2[lane];
    gp += __shfl_xor_sync(0xFFFFFFFFu, gp, 16);
    gp += __shfl_xor_sync(0xFFFFFFFFu, gp, 8);
    gp += __shfl_xor_sync(0xFFFFFFFFu, gp, 4);
    gp += __shfl_xor_sync(0xFFFFFFFFu, gp, 2);
    gp += __shfl_xor_sync(0xFFFFFFFFu, gp, 1);
    float g = 1.f / (1.f + expf(-(gp + bg2[0])));

    float w = expf(p * 0.17677669529663687f * g);   // 1/sqrt(32)
    if ((lane & 7) == 0) {
        int hd = lane >> 3;
        g_w[warp * HEADS + hd] = w;
        atomicAdd(&g_expsum[row * HEADS + hd], w);
    }
}

// ---------------- per-edge normalize + scatter-add of attn*v --------------
__global__ void edge_agg(const int* __restrict__ ei, int E) {
    int warp = (blockIdx.x * blockDim.x + threadIdx.x) >> 5;
    int lane = threadIdx.x & 31;
    if (warp >= E) return;
    int row = ei[warp];
    int col = ei[E + warp];
    int hd = lane >> 3;

    float w = g_w[warp * HEADS + hd];
    float ssum = g_expsum[row * HEADS + hd];
    float attn = w / (ssum + 1e-16f);

    float4 vv = *(const float4*)&g_v[col * HID + lane * 4];
    float* dst = &g_agg[row * HID + lane * 4];
    asm volatile("red.global.add.v4.f32 [%0], {%1,%2,%3,%4};"
                 :: "l"(dst), "f"(attn * vv.x), "f"(attn * vv.y),
                    "f"(attn * vv.z), "f"(attn * vv.w));
}

// ---------------- output projection: agg @ Wo^T + bo ----------------------
__global__ void out_gemm(const float* __restrict__ Wo,
                         const float* __restrict__ bo,
                         float* __restrict__ out, int n) {
    __shared__ __align__(16) float As[16][68];
    __shared__ __align__(16) float Bs[16][68];

    int m0 = blockIdx.x * 64;
    int cl0 = blockIdx.y * 64;

    int tid = threadIdx.y * 16 + threadIdx.x;
    int lk = tid & 15;
    int lr = tid >> 4;

    float acc[4][4];
#pragma unroll
    for (int i = 0; i < 4; i++)
#pragma unroll
        for (int j = 0; j < 4; j++) acc[i][j] = 0.f;

    for (int kk = 0; kk < HID; kk += 16) {
        int kc = kk + lk;
#pragma unroll
        for (int rr = 0; rr < 4; rr++) {
            int m = m0 + lr + rr * 16;
            As[lk][lr + rr * 16] = (m < n) ? g_agg[m * HID + kc] : 0.f;
        }
#pragma unroll
        for (int nn = 0; nn < 4; nn++) {
            int cc = lr + nn * 16;
            Bs[lk][cc] = Wo[(cl0 + cc) * HID + kc];
        }
        __syncthreads();
#pragma unroll
        for (int k = 0; k < 16; k++) {
            float a[4], b[4];
            *(float4*)a = *(const float4*)&As[k][threadIdx.y * 4];
            *(float4*)b = *(const float4*)&Bs[k][threadIdx.x * 4];
#pragma unroll
            for (int i = 0; i < 4; i++)
#pragma unroll
                for (int j = 0; j < 4; j++) acc[i][j] += a[i] * b[j];
        }
        __syncthreads();
    }
#pragma unroll
    for (int i = 0; i < 4; i++) {
        int m = m0 + threadIdx.y * 4 + i;
        if (m >= n) continue;
#pragma unroll
        for (int j = 0; j < 4; j++) {
            int c = cl0 + threadIdx.x * 4 + j;
            out[m * HID + c] = acc[i][j] + bo[c];
        }
    }
}

// ---------------- launch ---------------------------------------------------
extern "C" void kernel_launch(void* const* d_in, const int* in_sizes, int n_in,
                              void* d_out, int out_size) {
    const float* h    = (const float*)d_in[0];
    const float* frac = (const float*)d_in[1];
    const float* dist = (const float*)d_in[2];
    const int*   ei   = (const int*)d_in[3];
    const float* We   = (const float*)d_in[4];
    const float* be   = (const float*)d_in[5];
    const float* Wq   = (const float*)d_in[6];
    const float* bq   = (const float*)d_in[7];
    const float* Wk   = (const float*)d_in[8];
    const float* bk   = (const float*)d_in[9];
    const float* Wv   = (const float*)d_in[10];
    const float* bv   = (const float*)d_in[11];
    const float* Wo   = (const float*)d_in[12];
    const float* bo   = (const float*)d_in[13];
    const float* Wg1  = (const float*)d_in[14];
    const float* bg1  = (const float*)d_in[15];
    const float* Wg2  = (const float*)d_in[16];
    const float* bg2  = (const float*)d_in[17];

    int n = in_sizes[0] / HID;
    int E = in_sizes[2];
    float* out = (float*)d_out;

    zero_kernel<<<(n * HID + 1023) / 1024, 1024>>>(n);

    dim3 gA((n + 63) / 64, 6);
    qkv_gemm<<<gA, dim3(16, 16)>>>(h, frac, We, be, Wq, bq, Wk, bk, Wv, bv, n);

    int eblocks = (E + 7) / 8;   // 8 warps (edges) per 256-thread block
    edge_score<<<eblocks, 256>>>(ei, dist, Wg1, bg1, Wg2, bg2, E);
    edge_agg<<<eblocks, 256>>>(ei, E);

    dim3 gC((n + 63) / 64, 2);
    out_gemm<<<gC, dim3(16, 16)>>>(Wo, bo, out, n);
}

// round 2
// speedup vs baseline: 1.3302x; 1.3302x over previous
#include <cuda_runtime.h>
#include <math.h>

#define HID   128
#define HEADS 4
#define HDIM  32
#define NMAX  50176
#define EMAX  800000

// ---------------- scratch (device globals; no allocation allowed) ----------
__device__ float g_q[NMAX * HID];
__device__ float g_k[NMAX * HID];
__device__ float g_v[NMAX * HID];
__device__ float g_agg[NMAX * HID];     // unnormalized sum of w*v
__device__ float g_expsum[NMAX * HEADS];

// ---------------- zero scratch --------------------------------------------
__global__ void zero_kernel(int n) {
    int i = blockIdx.x * blockDim.x + threadIdx.x;
    if (i < n * HID) g_agg[i] = 0.f;
    if (i < n * HEADS) g_expsum[i] = 0.f;
}

// ---------------- fused h_combined + QKV projections ----------------------
// 128(M) x 64(N) tile per block, 256 threads, 8x4 accumulators.
// out[m][c] = sum_k (h[m][k] + frac[m]·We[k] + be[k]) * W[c][k] + bias[c]
__global__ void __launch_bounds__(256)
qkv_gemm(const float* __restrict__ h,
         const float* __restrict__ frac,
         const float* __restrict__ We,
         const float* __restrict__ be,
         const float* __restrict__ Wq, const float* __restrict__ bq,
         const float* __restrict__ Wk, const float* __restrict__ bk,
         const float* __restrict__ Wv, const float* __restrict__ bv,
         int n) {
    __shared__ __align__(16) float As[16][136];   // [k][m], padded
    __shared__ __align__(16) float Bs[16][68];    // [k][c]
    __shared__ float Fr[128][3];                  // frac rows for this block

    int m0 = blockIdx.x * 128;
    int c0 = blockIdx.y * 64;           // 0..320 within 384
    const float* W;
    const float* bias;
    float* outbuf;
    if (c0 < 128)      { W = Wq; bias = bq; outbuf = g_q; }
    else if (c0 < 256) { W = Wk; bias = bk; outbuf = g_k; }
    else               { W = Wv; bias = bv; outbuf = g_v; }
    int cl0 = c0 & 127;

    int tid = threadIdx.x;
    int lk  = tid & 15;     // k within chunk (A/B loads)
    int lg  = tid >> 4;     // group 0..15

    // stage frac rows (128 x 3)
    if (tid < 128) {
        int m = m0 + tid;
        if (m < n) {
            Fr[tid][0] = frac[m * 3 + 0];
            Fr[tid][1] = frac[m * 3 + 1];
            Fr[tid][2] = frac[m * 3 + 2];
        } else {
            Fr[tid][0] = Fr[tid][1] = Fr[tid][2] = 0.f;
        }
    }
    __syncthreads();

    float acc[8][4];
#pragma unroll
    for (int i = 0; i < 8; i++)
#pragma unroll
        for (int j = 0; j < 4; j++) acc[i][j] = 0.f;

    int ty = tid >> 4;      // 0..15 -> rows ty*8..ty*8+7
    int tx = tid & 15;      // 0..15 -> cols tx*4..tx*4+3

    for (int kk = 0; kk < HID; kk += 16) {
        int kc = kk + lk;
        float w0 = We[kc * 3 + 0], w1 = We[kc * 3 + 1], w2 = We[kc * 3 + 2];
        float bek = be[kc];
        // A tile: 16 k x 128 m, 8 elements/thread, fused frac embedding
#pragma unroll
        for (int rr = 0; rr < 8; rr++) {
            int ml = lg + rr * 16;
            int m = m0 + ml;
            float x = 0.f;
            if (m < n) {
                x = h[m * HID + kc] + Fr[ml][0] * w0 + Fr[ml][1] * w1
                    + Fr[ml][2] * w2 + bek;
            }
            As[lk][ml] = x;
        }
        // B tile: 16 k x 64 c, 4 elements/thread
#pragma unroll
        for (int nn = 0; nn < 4; nn++) {
            int cc = lg + nn * 16;
            Bs[lk][cc] = W[(cl0 + cc) * HID + kc];
        }
        __syncthreads();
#pragma unroll
        for (int k = 0; k < 16; k++) {
            float a[8], b[4];
            *(float4*)&a[0] = *(const float4*)&As[k][ty * 8];
            *(float4*)&a[4] = *(const float4*)&As[k][ty * 8 + 4];
            *(float4*)&b[0] = *(const float4*)&Bs[k][tx * 4];
#pragma unroll
            for (int i = 0; i < 8; i++)
#pragma unroll
                for (int j = 0; j < 4; j++) acc[i][j] = fmaf(a[i], b[j], acc[i][j]);
        }
        __syncthreads();
    }
#pragma unroll
    for (int i = 0; i < 8; i++) {
        int m = m0 + ty * 8 + i;
        if (m >= n) continue;
#pragma unroll
        for (int j = 0; j < 4; j++) {
            int c = cl0 + tx * 4 + j;
            outbuf[m * HID + c] = acc[i][j] + bias[c];
        }
    }
}

// ---------------- fused per-edge: score + gate + exp + scatter w*v --------
// one warp per edge; softmax max-shift skipped (scores O(1), ratio identical);
// normalization deferred to out_gemm (divide by expsum per node/head).
__global__ void edge_fused(const int* __restrict__ ei,
                           const float* __restrict__ dist,
                           const float* __restrict__ Wg1, const float* __restrict__ bg1,
                           const float* __restrict__ Wg2, const float* __restrict__ bg2,
                           int E) {
    int warp = (blockIdx.x * blockDim.x + threadIdx.x) >> 5;
    int lane = threadIdx.x & 31;
    if (warp >= E) return;
    int row = __ldg(&ei[warp]);
    int col = __ldg(&ei[E + warp]);

    float4 qv = *(const float4*)&g_q[row * HID + lane * 4];
    float4 kv = *(const float4*)&g_k[col * HID + lane * 4];
    float4 vv = *(const float4*)&g_v[col * HID + lane * 4];

    float p = qv.x * kv.x + qv.y * kv.y + qv.z * kv.z + qv.w * kv.w;
    // reduce within 8-lane groups (one head per group)
    p += __shfl_xor_sync(0xFFFFFFFFu, p, 1);
    p += __shfl_xor_sync(0xFFFFFFFFu, p, 2);
    p += __shfl_xor_sync(0xFFFFFFFFu, p, 4);

    // gate MLP: 1 -> 32 (silu) -> 1 (sigmoid); lane l = hidden unit l
    float d = dist[warp];
    float t = fmaf(d, Wg1[lane], bg1[lane]);
    float hsi = t / (1.f + __expf(-t));
    float gp = hsi * Wg2[lane];
    gp += __shfl_xor_sync(0xFFFFFFFFu, gp, 16);
    gp += __shfl_xor_sync(0xFFFFFFFFu, gp, 8);
    gp += __shfl_xor_sync(0xFFFFFFFFu, gp, 4);
    gp += __shfl_xor_sync(0xFFFFFFFFu, gp, 2);
    gp += __shfl_xor_sync(0xFFFFFFFFu, gp, 1);
    float g = 1.f / (1.f + __expf(-(gp + bg2[0])));

    float w = __expf(p * 0.17677669529663687f * g);   // 1/sqrt(32)

    float* dst = &g_agg[row * HID + lane * 4];
    asm volatile("red.global.add.v4.f32 [%0], {%1,%2,%3,%4};"
                 :: "l"(dst), "f"(w * vv.x), "f"(w * vv.y),
                    "f"(w * vv.z), "f"(w * vv.w));
    if ((lane & 7) == 0)
        atomicAdd(&g_expsum[row * HEADS + (lane >> 3)], w);
}

// ---------------- output projection: (agg/expsum) @ Wo^T + bo -------------
__global__ void __launch_bounds__(256)
out_gemm(const float* __restrict__ Wo,
         const float* __restrict__ bo,
         float* __restrict__ out, int n) {
    __shared__ __align__(16) float As[16][136];
    __shared__ __align__(16) float Bs[16][68];
    __shared__ float Inv[128][4];

    int m0 = blockIdx.x * 128;
    int cl0 = blockIdx.y * 64;

    int tid = threadIdx.x;
    int lk  = tid & 15;
    int lg  = tid >> 4;

    // stage 1/(expsum+eps) for 128 rows x 4 heads
    for (int t = tid; t < 128 * HEADS; t += 256) {
        int ml = t >> 2, hd = t & 3;
        int m = m0 + ml;
        Inv[ml][hd] = (m < n) ? 1.f / (g_expsum[m * HEADS + hd] + 1e-16f) : 0.f;
    }
    __syncthreads();

    float acc[8][4];
#pragma unroll
    for (int i = 0; i < 8; i++)
#pragma unroll
        for (int j = 0; j < 4; j++) acc[i][j] = 0.f;

    int ty = tid >> 4;
    int tx = tid & 15;

    for (int kk = 0; kk < HID; kk += 16) {
        int kc = kk + lk;
        int hd = kc >> 5;
#pragma unroll
        for (int rr = 0; rr < 8; rr++) {
            int ml = lg + rr * 16;
            int m = m0 + ml;
            As[lk][ml] = (m < n) ? g_agg[m * HID + kc] * Inv[ml][hd] : 0.f;
        }
#pragma unroll
        for (int nn = 0; nn < 4; nn++) {
            int cc = lg + nn * 16;
            Bs[lk][cc] = Wo[(cl0 + cc) * HID + kc];
        }
        __syncthreads();
#pragma unroll
        for (int k = 0; k < 16; k++) {
            float a[8], b[4];
            *(float4*)&a[0] = *(const float4*)&As[k][ty * 8];
            *(float4*)&a[4] = *(const float4*)&As[k][ty * 8 + 4];
            *(float4*)&b[0] = *(const float4*)&Bs[k][tx * 4];
#pragma unroll
            for (int i = 0; i < 8; i++)
#pragma unroll
                for (int j = 0; j < 4; j++) acc[i][j] = fmaf(a[i], b[j], acc[i][j]);
        }
        __syncthreads();
    }
#pragma unroll
    for (int i = 0; i < 8; i++) {
        int m = m0 + ty * 8 + i;
        if (m >= n) continue;
#pragma unroll
        for (int j = 0; j < 4; j++) {
            int c = cl0 + tx * 4 + j;
            out[m * HID + c] = acc[i][j] + bo[c];
        }
    }
}

// ---------------- launch ---------------------------------------------------
extern "C" void kernel_launch(void* const* d_in, const int* in_sizes, int n_in,
                              void* d_out, int out_size) {
    const float* h    = (const float*)d_in[0];
    const float* frac = (const float*)d_in[1];
    const float* dist = (const float*)d_in[2];
    const int*   ei   = (const int*)d_in[3];
    const float* We   = (const float*)d_in[4];
    const float* be   = (const float*)d_in[5];
    const float* Wq   = (const float*)d_in[6];
    const float* bq   = (const float*)d_in[7];
    const float* Wk   = (const float*)d_in[8];
    const float* bk   = (const float*)d_in[9];
    const float* Wv   = (const float*)d_in[10];
    const float* bv   = (const float*)d_in[11];
    const float* Wo   = (const float*)d_in[12];
    const float* bo   = (const float*)d_in[13];
    const float* Wg1  = (const float*)d_in[14];
    const float* bg1  = (const float*)d_in[15];
    const float* Wg2  = (const float*)d_in[16];
    const float* bg2  = (const float*)d_in[17];

    int n = in_sizes[0] / HID;
    int E = in_sizes[2];
    float* out = (float*)d_out;

    zero_kernel<<<(n * HID + 1023) / 1024, 1024>>>(n);

    dim3 gA((n + 127) / 128, 6);
    qkv_gemm<<<gA, 256>>>(h, frac, We, be, Wq, bq, Wk, bk, Wv, bv, n);

    int eblocks = (E + 7) / 8;   // 8 warps (edges) per 256-thread block
    edge_fused<<<eblocks, 256>>>(ei, dist, Wg1, bg1, Wg2, bg2, E);

    dim3 gC((n + 127) / 128, 2);
    out_gemm<<<gC, 256>>>(Wo, bo, out, n);
}

// round 3
// speedup vs baseline: 1.4421x; 1.0841x over previous
#include <cuda_runtime.h>
#include <cuda_fp16.h>
#include <math.h>

#define HID   128
#define HEADS 4
#define HDIM  32
#define NMAX  50176
#define EMAX  800000

typedef unsigned long long ull;

// ---------------- scratch ---------------------------------------------------
__device__ __half g_qh[NMAX * HID];
__device__ __half g_kh[NMAX * HID];
__device__ __half g_vh[NMAX * HID];
__device__ float  g_agg[NMAX * HID];     // unnormalized sum of w*v (fp32 atomics)
__device__ float  g_expsum[NMAX * HEADS];

// ---------------- packed f32x2 helpers --------------------------------------
__device__ __forceinline__ void ffma2(ull& d, ull a, ull b) {
    asm("fma.rn.f32x2 %0, %1, %2, %3;" : "=l"(d) : "l"(a), "l"(b), "l"(d));
}
__device__ __forceinline__ ull pack2(float lo, float hi) {
    ull d;
    asm("mov.b64 %0, {%1, %2};" : "=l"(d) : "f"(lo), "f"(hi));
    return d;
}
__device__ __forceinline__ void unpack2(ull d, float& lo, float& hi) {
    asm("mov.b64 {%0, %1}, %2;" : "=f"(lo), "=f"(hi) : "l"(d));
}

// ---------------- zero scratch ----------------------------------------------
__global__ void zero_kernel(int n) {
    int i = blockIdx.x * blockDim.x + threadIdx.x;
    if (i < n * HID) g_agg[i] = 0.f;
    if (i < n * HEADS) g_expsum[i] = 0.f;
}

// ---------------- fused h_combined + QKV projections ------------------------
// 128(M) x 128(N) tile per block, 256 threads, 8x8 per-thread (f32x2 packed).
// blockIdx.y selects projection: 0=Q, 1=K, 2=V.  Output stored as fp16.
__global__ void __launch_bounds__(256, 2)
qkv_gemm(const float* __restrict__ h,
         const float* __restrict__ frac,
         const float* __restrict__ We,
         const float* __restrict__ be,
         const float* __restrict__ Wq, const float* __restrict__ bq,
         const float* __restrict__ Wk, const float* __restrict__ bk,
         const float* __restrict__ Wv, const float* __restrict__ bv,
         int n) {
    __shared__ __align__(16) float As[16][136];   // [k][m]
    __shared__ __align__(16) float Bs[16][136];   // [k][c]
    __shared__ float Fr[128][3];

    int m0 = blockIdx.x * 128;
    const float* W; const float* bias; __half* outbuf;
    if (blockIdx.y == 0)      { W = Wq; bias = bq; outbuf = g_qh; }
    else if (blockIdx.y == 1) { W = Wk; bias = bk; outbuf = g_kh; }
    else                      { W = Wv; bias = bv; outbuf = g_vh; }

    int tid = threadIdx.x;
    int lk  = tid & 15;     // k within chunk
    int lg  = tid >> 4;     // group 0..15

    if (tid < 128) {
        int m = m0 + tid;
        if (m < n) {
            Fr[tid][0] = frac[m * 3 + 0];
            Fr[tid][1] = frac[m * 3 + 1];
            Fr[tid][2] = frac[m * 3 + 2];
        } else {
            Fr[tid][0] = Fr[tid][1] = Fr[tid][2] = 0.f;
        }
    }
    __syncthreads();

    ull acc2[8][4];         // 8 rows x 4 col-pairs
#pragma unroll
    for (int i = 0; i < 8; i++)
#pragma unroll
        for (int j = 0; j < 4; j++) acc2[i][j] = 0ull;

    int ty = tid >> 4;      // rows ty*8 .. +7
    int tx = tid & 15;      // cols tx*8 .. +7

    for (int kk = 0; kk < HID; kk += 16) {
        int kc = kk + lk;
        float w0 = We[kc * 3 + 0], w1 = We[kc * 3 + 1], w2 = We[kc * 3 + 2];
        float bek = be[kc];
#pragma unroll
        for (int rr = 0; rr < 8; rr++) {
            int ml = lg + rr * 16;
            int m = m0 + ml;
            float x = 0.f;
            if (m < n)
                x = h[m * HID + kc] + Fr[ml][0] * w0 + Fr[ml][1] * w1
                    + Fr[ml][2] * w2 + bek;
            As[lk][ml] = x;
        }
#pragma unroll
        for (int nn = 0; nn < 8; nn++) {
            int cc = lg + nn * 16;
            Bs[lk][cc] = W[cc * HID + kc];
        }
        __syncthreads();
#pragma unroll
        for (int k = 0; k < 16; k++) {
            float a[8];
            *(float4*)&a[0] = *(const float4*)&As[k][ty * 8];
            *(float4*)&a[4] = *(const float4*)&As[k][ty * 8 + 4];
            ull b2[4];
            {
                ulonglong2 t0 = *(const ulonglong2*)&Bs[k][tx * 8];
                ulonglong2 t1 = *(const ulonglong2*)&Bs[k][tx * 8 + 4];
                b2[0] = t0.x; b2[1] = t0.y; b2[2] = t1.x; b2[3] = t1.y;
            }
#pragma unroll
            for (int i = 0; i < 8; i++) {
                ull ab = pack2(a[i], a[i]);
#pragma unroll
                for (int j = 0; j < 4; j++) ffma2(acc2[i][j], ab, b2[j]);
            }
        }
        __syncthreads();
    }
#pragma unroll
    for (int i = 0; i < 8; i++) {
        int m = m0 + ty * 8 + i;
        if (m >= n) continue;
        __half2* dst = (__half2*)&outbuf[m * HID + tx * 8];
#pragma unroll
        for (int j = 0; j < 4; j++) {
            float c0, c1;
            unpack2(acc2[i][j], c0, c1);
            int c = tx * 8 + j * 2;
            dst[j] = __floats2half2_rn(c0 + bias[c], c1 + bias[c + 1]);
        }
    }
}

// ---------------- fused per-edge: score + gate + exp + scatter w*v ----------
union H4 { float2 f; __half2 h[2]; };

__global__ void edge_fused(const int* __restrict__ ei,
                           const float* __restrict__ dist,
                           const float* __restrict__ Wg1, const float* __restrict__ bg1,
                           const float* __restrict__ Wg2, const float* __restrict__ bg2,
                           int E) {
    int warp = (blockIdx.x * blockDim.x + threadIdx.x) >> 5;
    int lane = threadIdx.x & 31;
    if (warp >= E) return;
    int row = __ldg(&ei[warp]);
    int col = __ldg(&ei[E + warp]);

    H4 q4, k4, v4;
    q4.f = *(const float2*)&g_qh[row * HID + lane * 4];
    k4.f = *(const float2*)&g_kh[col * HID + lane * 4];
    v4.f = *(const float2*)&g_vh[col * HID + lane * 4];

    float2 q0 = __half22float2(q4.h[0]), q1 = __half22float2(q4.h[1]);
    float2 k0 = __half22float2(k4.h[0]), k1 = __half22float2(k4.h[1]);
    float p = q0.x * k0.x + q0.y * k0.y + q1.x * k1.x + q1.y * k1.y;
    // reduce within 8-lane groups (one head per group)
    p += __shfl_xor_sync(0xFFFFFFFFu, p, 1);
    p += __shfl_xor_sync(0xFFFFFFFFu, p, 2);
    p += __shfl_xor_sync(0xFFFFFFFFu, p, 4);

    // gate MLP: 1 -> 32 (silu) -> 1 (sigmoid)
    float d = dist[warp];
    float t = fmaf(d, Wg1[lane], bg1[lane]);
    float hsi = t / (1.f + __expf(-t));
    float gp = hsi * Wg2[lane];
    gp += __shfl_xor_sync(0xFFFFFFFFu, gp, 16);
    gp += __shfl_xor_sync(0xFFFFFFFFu, gp, 8);
    gp += __shfl_xor_sync(0xFFFFFFFFu, gp, 4);
    gp += __shfl_xor_sync(0xFFFFFFFFu, gp, 2);
    gp += __shfl_xor_sync(0xFFFFFFFFu, gp, 1);
    float g = 1.f / (1.f + __expf(-(gp + bg2[0])));

    float w = __expf(p * 0.17677669529663687f * g);   // 1/sqrt(32)

    float2 v0 = __half22float2(v4.h[0]), v1 = __half22float2(v4.h[1]);
    float* dst = &g_agg[row * HID + lane * 4];
    asm volatile("red.global.add.v4.f32 [%0], {%1,%2,%3,%4};"
                 :: "l"(dst), "f"(w * v0.x), "f"(w * v0.y),
                    "f"(w * v1.x), "f"(w * v1.y));
    if ((lane & 7) == 0)
        atomicAdd(&g_expsum[row * HEADS + (lane >> 3)], w);
}

// ---------------- output projection: (agg/expsum) @ Wo^T + bo ---------------
__global__ void __launch_bounds__(256, 2)
out_gemm(const float* __restrict__ Wo,
         const float* __restrict__ bo,
         float* __restrict__ out, int n) {
    __shared__ __align__(16) float As[16][136];
    __shared__ __align__(16) float Bs[16][136];
    __shared__ float Inv[128][4];

    int m0 = blockIdx.x * 128;
    int tid = threadIdx.x;
    int lk  = tid & 15;
    int lg  = tid >> 4;

    for (int t = tid; t < 128 * HEADS; t += 256) {
        int ml = t >> 2, hd = t & 3;
        int m = m0 + ml;
        Inv[ml][hd] = (m < n) ? 1.f / (g_expsum[m * HEADS + hd] + 1e-16f) : 0.f;
    }
    __syncthreads();

    ull acc2[8][4];
#pragma unroll
    for (int i = 0; i < 8; i++)
#pragma unroll
        for (int j = 0; j < 4; j++) acc2[i][j] = 0ull;

    int ty = tid >> 4;
    int tx = tid & 15;

    for (int kk = 0; kk < HID; kk += 16) {
        int kc = kk + lk;
        int hd = kc >> 5;
#pragma unroll
        for (int rr = 0; rr < 8; rr++) {
            int ml = lg + rr * 16;
            int m = m0 + ml;
            As[lk][ml] = (m < n) ? g_agg[m * HID + kc] * Inv[ml][hd] : 0.f;
        }
#pragma unroll
        for (int nn = 0; nn < 8; nn++) {
            int cc = lg + nn * 16;
            Bs[lk][cc] = Wo[cc * HID + kc];
        }
        __syncthreads();
#pragma unroll
        for (int k = 0; k < 16; k++) {
            float a[8];
            *(float4*)&a[0] = *(const float4*)&As[k][ty * 8];
            *(float4*)&a[4] = *(const float4*)&As[k][ty * 8 + 4];
            ull b2[4];
            {
                ulonglong2 t0 = *(const ulonglong2*)&Bs[k][tx * 8];
                ulonglong2 t1 = *(const ulonglong2*)&Bs[k][tx * 8 + 4];
                b2[0] = t0.x; b2[1] = t0.y; b2[2] = t1.x; b2[3] = t1.y;
            }
#pragma unroll
            for (int i = 0; i < 8; i++) {
                ull ab = pack2(a[i], a[i]);
#pragma unroll
                for (int j = 0; j < 4; j++) ffma2(acc2[i][j], ab, b2[j]);
            }
        }
        __syncthreads();
    }
#pragma unroll
    for (int i = 0; i < 8; i++) {
        int m = m0 + ty * 8 + i;
        if (m >= n) continue;
#pragma unroll
        for (int j = 0; j < 4; j++) {
            float c0, c1;
            unpack2(acc2[i][j], c0, c1);
            int c = tx * 8 + j * 2;
            out[m * HID + c]     = c0 + bo[c];
            out[m * HID + c + 1] = c1 + bo[c + 1];
        }
    }
}

// ---------------- launch ----------------------------------------------------
extern "C" void kernel_launch(void* const* d_in, const int* in_sizes, int n_in,
                              void* d_out, int out_size) {
    const float* h    = (const float*)d_in[0];
    const float* frac = (const float*)d_in[1];
    const float* dist = (const float*)d_in[2];
    const int*   ei   = (const int*)d_in[3];
    const float* We   = (const float*)d_in[4];
    const float* be   = (const float*)d_in[5];
    const float* Wq   = (const float*)d_in[6];
    const float* bq   = (const float*)d_in[7];
    const float* Wk   = (const float*)d_in[8];
    const float* bk   = (const float*)d_in[9];
    const float* Wv   = (const float*)d_in[10];
    const float* bv   = (const float*)d_in[11];
    const float* Wo   = (const float*)d_in[12];
    const float* bo   = (const float*)d_in[13];
    const float* Wg1  = (const float*)d_in[14];
    const float* bg1  = (const float*)d_in[15];
    const float* Wg2  = (const float*)d_in[16];
    const float* bg2  = (const float*)d_in[17];

    int n = in_sizes[0] / HID;
    int E = in_sizes[2];
    float* out = (float*)d_out;

    zero_kernel<<<(n * HID + 1023) / 1024, 1024>>>(n);

    dim3 gA((n + 127) / 128, 3);
    qkv_gemm<<<gA, 256>>>(h, frac, We, be, Wq, bq, Wk, bk, Wv, bv, n);

    int eblocks = (E + 7) / 8;
    edge_fused<<<eblocks, 256>>>(ei, dist, Wg1, bg1, Wg2, bg2, E);

    out_gemm<<<(n + 127) / 128, 256>>>(Wo, bo, out, n);
}

// round 5
// speedup vs baseline: 2.1193x; 1.4696x over previous
#include <cuda_runtime.h>
#include <cuda_fp16.h>
#include <math.h>

#define HID   128
#define HEADS 4
#define HDIM  32
#define NMAX  50176
#define EMAX  800000

// ---------------- scratch ---------------------------------------------------
__device__ __half g_qh[NMAX * HID];
__device__ __half g_kh[NMAX * HID];
__device__ __half g_vh[NMAX * HID];
__device__ float  g_agg[NMAX * HID];     // unnormalized sum of w*v (fp32 atomics)
__device__ float  g_expsum[NMAX * HEADS];

// ---------------- mma helpers -----------------------------------------------
__device__ __forceinline__ unsigned smem_u32(const void* p) {
    return (unsigned)__cvta_generic_to_shared(p);
}
__device__ __forceinline__ void ldsm_x4(unsigned& r0, unsigned& r1,
                                        unsigned& r2, unsigned& r3, unsigned a) {
    asm volatile("ldmatrix.sync.aligned.m8n8.x4.shared.b16 {%0,%1,%2,%3},[%4];"
                 : "=r"(r0), "=r"(r1), "=r"(r2), "=r"(r3) : "r"(a));
}
__device__ __forceinline__ void mma16816(float* c, const unsigned* a, const unsigned* b) {
    asm volatile(
        "mma.sync.aligned.m16n8k16.row.col.f32.f16.f16.f32 "
        "{%0,%1,%2,%3},{%4,%5,%6,%7},{%8,%9},{%0,%1,%2,%3};"
        : "+f"(c[0]), "+f"(c[1]), "+f"(c[2]), "+f"(c[3])
        : "r"(a[0]), "r"(a[1]), "r"(a[2]), "r"(a[3]), "r"(b[0]), "r"(b[1]));
}

#define AK 72   // padded K stride (halves) for smem tiles

// ---------------- zero scratch ----------------------------------------------
__global__ void zero_kernel(int n) {
    int i = blockIdx.x * blockDim.x + threadIdx.x;
    if (i < n * HID) g_agg[i] = 0.f;
    if (i < n * HEADS) g_expsum[i] = 0.f;
}

// ---------------- fused h_combined + QKV projections (tensor cores) ---------
// 128(M) x 128(N) per block, 8 warps x (32x64), K in 2 chunks of 64.
// blockIdx.y: 0=Q, 1=K, 2=V. Output fp16.
__global__ void __launch_bounds__(256, 2)
qkv_gemm(const float* __restrict__ h,
         const float* __restrict__ frac,
         const float* __restrict__ We,
         const float* __restrict__ be,
         const float* __restrict__ Wq, const float* __restrict__ bq,
         const float* __restrict__ Wk, const float* __restrict__ bk,
         const float* __restrict__ Wv, const float* __restrict__ bv,
         int n) {
    __shared__ __align__(16) __half As[128][AK];
    __shared__ __align__(16) __half Bs[128][AK];
    __shared__ float Wes[128][4];   // We0,We1,We2,be
    __shared__ float Fr[128][4];    // frac x,y,z

    int m0 = blockIdx.x * 128;
    const float* W; const float* bias; __half* outbuf;
    if (blockIdx.y == 0)      { W = Wq; bias = bq; outbuf = g_qh; }
    else if (blockIdx.y == 1) { W = Wk; bias = bk; outbuf = g_kh; }
    else                      { W = Wv; bias = bv; outbuf = g_vh; }

    int tid = threadIdx.x;
    int wid = tid >> 5, lane = tid & 31;
    int wm = (wid & 3) * 32;        // warp row base
    int wn = (wid >> 2) * 64;       // warp col base

    if (tid < 128) {
        int kc = tid;
        Wes[kc][0] = We[kc * 3 + 0];
        Wes[kc][1] = We[kc * 3 + 1];
        Wes[kc][2] = We[kc * 3 + 2];
        Wes[kc][3] = be[kc];
        int m = m0 + tid;
        if (m < n) {
            Fr[tid][0] = frac[m * 3 + 0];
            Fr[tid][1] = frac[m * 3 + 1];
            Fr[tid][2] = frac[m * 3 + 2];
        } else {
            Fr[tid][0] = Fr[tid][1] = Fr[tid][2] = 0.f;
        }
    }

    float acc[2][8][4];
#pragma unroll
    for (int i = 0; i < 2; i++)
#pragma unroll
        for (int j = 0; j < 8; j++)
#pragma unroll
            for (int t = 0; t < 4; t++) acc[i][j][t] = 0.f;

    __syncthreads();

    for (int k0 = 0; k0 < HID; k0 += 64) {
        // A tile: h_combined[m0..+127][k0..+63] -> fp16
        for (int idx = tid; idx < 128 * 16; idx += 256) {
            int r = idx >> 4;
            int k4 = (idx & 15) * 4;
            int m = m0 + r;
            float x[4] = {0.f, 0.f, 0.f, 0.f};
            if (m < n) {
                float4 hv = *(const float4*)&h[m * HID + k0 + k4];
                float f0 = Fr[r][0], f1 = Fr[r][1], f2 = Fr[r][2];
                x[0] = hv.x; x[1] = hv.y; x[2] = hv.z; x[3] = hv.w;
#pragma unroll
                for (int u = 0; u < 4; u++) {
                    int kc = k0 + k4 + u;
                    x[u] += f0 * Wes[kc][0] + f1 * Wes[kc][1] + f2 * Wes[kc][2] + Wes[kc][3];
                }
            }
            __half2* dst = (__half2*)&As[r][k4];
            dst[0] = __floats2half2_rn(x[0], x[1]);
            dst[1] = __floats2half2_rn(x[2], x[3]);
        }
        // B tile: W[c][k0..+63] -> fp16
        for (int idx = tid; idx < 128 * 16; idx += 256) {
            int c = idx >> 4;
            int k4 = (idx & 15) * 4;
            float4 wv = *(const float4*)&W[c * HID + k0 + k4];
            __half2* dst = (__half2*)&Bs[c][k4];
            dst[0] = __floats2half2_rn(wv.x, wv.y);
            dst[1] = __floats2half2_rn(wv.z, wv.w);
        }
        __syncthreads();

#pragma unroll
        for (int ks = 0; ks < 64; ks += 16) {
            unsigned af[2][4];
#pragma unroll
            for (int mf = 0; mf < 2; mf++) {
                unsigned a = smem_u32(&As[wm + mf * 16 + (lane & 15)][ks + (lane >> 4) * 8]);
                ldsm_x4(af[mf][0], af[mf][1], af[mf][2], af[mf][3], a);
            }
            // B fragment: Bs is [n][k]  (= B col-major) -> NON-trans ldmatrix,
            // same addressing as A. r0=(n0-8,klo) r1=(n8-16,klo) r2=(n0-8,khi) r3=(n8-16,khi)
            unsigned bf[8][2];
#pragma unroll
            for (int ng = 0; ng < 4; ng++) {
                unsigned a = smem_u32(&Bs[wn + ng * 16 + (lane & 15)][ks + (lane >> 4) * 8]);
                unsigned r0, r1, r2, r3;
                ldsm_x4(r0, r1, r2, r3, a);
                bf[ng * 2][0] = r0; bf[ng * 2][1] = r2;
                bf[ng * 2 + 1][0] = r1; bf[ng * 2 + 1][1] = r3;
            }
#pragma unroll
            for (int mf = 0; mf < 2; mf++)
#pragma unroll
                for (int nf = 0; nf < 8; nf++)
                    mma16816(acc[mf][nf], af[mf], bf[nf]);
        }
        __syncthreads();
    }

    // epilogue: add bias, store fp16
#pragma unroll
    for (int mf = 0; mf < 2; mf++) {
        int r0 = m0 + wm + mf * 16 + (lane >> 2);
#pragma unroll
        for (int nf = 0; nf < 8; nf++) {
            int c = wn + nf * 8 + (lane & 3) * 2;
            float b0 = bias[c], b1 = bias[c + 1];
            if (r0 < n)
                *(__half2*)&outbuf[r0 * HID + c] =
                    __floats2half2_rn(acc[mf][nf][0] + b0, acc[mf][nf][1] + b1);
            if (r0 + 8 < n)
                *(__half2*)&outbuf[(r0 + 8) * HID + c] =
                    __floats2half2_rn(acc[mf][nf][2] + b0, acc[mf][nf][3] + b1);
        }
    }
}

// ---------------- fused per-edge: score + gate + exp + scatter w*v ----------
union H4 { float2 f; __half2 h[2]; };

__global__ void edge_fused(const int* __restrict__ ei,
                           const float* __restrict__ dist,
                           const float* __restrict__ Wg1, const float* __restrict__ bg1,
                           const float* __restrict__ Wg2, const float* __restrict__ bg2,
                           int E) {
    int warp = (blockIdx.x * blockDim.x + threadIdx.x) >> 5;
    int lane = threadIdx.x & 31;
    if (warp >= E) return;
    int row = __ldg(&ei[warp]);
    int col = __ldg(&ei[E + warp]);

    H4 q4, k4, v4;
    q4.f = *(const float2*)&g_qh[row * HID + lane * 4];
    k4.f = *(const float2*)&g_kh[col * HID + lane * 4];
    v4.f = *(const float2*)&g_vh[col * HID + lane * 4];

    float2 q0 = __half22float2(q4.h[0]), q1 = __half22float2(q4.h[1]);
    float2 k0 = __half22float2(k4.h[0]), k1 = __half22float2(k4.h[1]);
    float p = q0.x * k0.x + q0.y * k0.y + q1.x * k1.x + q1.y * k1.y;
    p += __shfl_xor_sync(0xFFFFFFFFu, p, 1);
    p += __shfl_xor_sync(0xFFFFFFFFu, p, 2);
    p += __shfl_xor_sync(0xFFFFFFFFu, p, 4);

    // gate MLP: 1 -> 32 (silu) -> 1 (sigmoid)
    float d = dist[warp];
    float t = fmaf(d, Wg1[lane], bg1[lane]);
    float hsi = t / (1.f + __expf(-t));
    float gp = hsi * Wg2[lane];
    gp += __shfl_xor_sync(0xFFFFFFFFu, gp, 16);
    gp += __shfl_xor_sync(0xFFFFFFFFu, gp, 8);
    gp += __shfl_xor_sync(0xFFFFFFFFu, gp, 4);
    gp += __shfl_xor_sync(0xFFFFFFFFu, gp, 2);
    gp += __shfl_xor_sync(0xFFFFFFFFu, gp, 1);
    float g = 1.f / (1.f + __expf(-(gp + bg2[0])));

    float w = __expf(p * 0.17677669529663687f * g);   // 1/sqrt(32)

    float2 v0 = __half22float2(v4.h[0]), v1 = __half22float2(v4.h[1]);
    float* dst = &g_agg[row * HID + lane * 4];
    asm volatile("red.global.add.v4.f32 [%0], {%1,%2,%3,%4};"
                 :: "l"(dst), "f"(w * v0.x), "f"(w * v0.y),
                    "f"(w * v1.x), "f"(w * v1.y));
    if ((lane & 7) == 0)
        atomicAdd(&g_expsum[row * HEADS + (lane >> 3)], w);
}

// ---------------- output projection: (agg/expsum) @ Wo^T + bo (tensor) ------
__global__ void __launch_bounds__(256, 2)
out_gemm(const float* __restrict__ Wo,
         const float* __restrict__ bo,
         float* __restrict__ out, int n) {
    __shared__ __align__(16) __half As[128][AK];
    __shared__ __align__(16) __half Bs[128][AK];
    __shared__ float Inv[128][4];

    int m0 = blockIdx.x * 128;
    int tid = threadIdx.x;
    int wid = tid >> 5, lane = tid & 31;
    int wm = (wid & 3) * 32;
    int wn = (wid >> 2) * 64;

    for (int t = tid; t < 128 * HEADS; t += 256) {
        int ml = t >> 2, hd = t & 3;
        int m = m0 + ml;
        Inv[ml][hd] = (m < n) ? 1.f / (g_expsum[m * HEADS + hd] + 1e-16f) : 0.f;
    }

    float acc[2][8][4];
#pragma unroll
    for (int i = 0; i < 2; i++)
#pragma unroll
        for (int j = 0; j < 8; j++)
#pragma unroll
            for (int t = 0; t < 4; t++) acc[i][j][t] = 0.f;

    __syncthreads();

    for (int k0 = 0; k0 < HID; k0 += 64) {
        for (int idx = tid; idx < 128 * 16; idx += 256) {
            int r = idx >> 4;
            int k4 = (idx & 15) * 4;
            int m = m0 + r;
            float x[4] = {0.f, 0.f, 0.f, 0.f};
            if (m < n) {
                float4 av = *(const float4*)&g_agg[m * HID + k0 + k4];
                float iv = Inv[r][(k0 + k4) >> 5];   // 4 consecutive k share a head
                x[0] = av.x * iv; x[1] = av.y * iv; x[2] = av.z * iv; x[3] = av.w * iv;
            }
            __half2* dst = (__half2*)&As[r][k4];
            dst[0] = __floats2half2_rn(x[0], x[1]);
            dst[1] = __floats2half2_rn(x[2], x[3]);
        }
        for (int idx = tid; idx < 128 * 16; idx += 256) {
            int c = idx >> 4;
            int k4 = (idx & 15) * 4;
            float4 wv = *(const float4*)&Wo[c * HID + k0 + k4];
            __half2* dst = (__half2*)&Bs[c][k4];
            dst[0] = __floats2half2_rn(wv.x, wv.y);
            dst[1] = __floats2half2_rn(wv.z, wv.w);
        }
        __syncthreads();

#pragma unroll
        for (int ks = 0; ks < 64; ks += 16) {
            unsigned af[2][4];
#pragma unroll
            for (int mf = 0; mf < 2; mf++) {
                unsigned a = smem_u32(&As[wm + mf * 16 + (lane & 15)][ks + (lane >> 4) * 8]);
                ldsm_x4(af[mf][0], af[mf][1], af[mf][2], af[mf][3], a);
            }
            unsigned bf[8][2];
#pragma unroll
            for (int ng = 0; ng < 4; ng++) {
                unsigned a = smem_u32(&Bs[wn + ng * 16 + (lane & 15)][ks + (lane >> 4) * 8]);
                unsigned r0, r1, r2, r3;
                ldsm_x4(r0, r1, r2, r3, a);
                bf[ng * 2][0] = r0; bf[ng * 2][1] = r2;
                bf[ng * 2 + 1][0] = r1; bf[ng * 2 + 1][1] = r3;
            }
#pragma unroll
            for (int mf = 0; mf < 2; mf++)
#pragma unroll
                for (int nf = 0; nf < 8; nf++)
                    mma16816(acc[mf][nf], af[mf], bf[nf]);
        }
        __syncthreads();
    }

#pragma unroll
    for (int mf = 0; mf < 2; mf++) {
        int r0 = m0 + wm + mf * 16 + (lane >> 2);
#pragma unroll
        for (int nf = 0; nf < 8; nf++) {
            int c = wn + nf * 8 + (lane & 3) * 2;
            float b0 = bo[c], b1 = bo[c + 1];
            if (r0 < n)
                *(float2*)&out[r0 * HID + c] =
                    make_float2(acc[mf][nf][0] + b0, acc[mf][nf][1] + b1);
            if (r0 + 8 < n)
                *(float2*)&out[(r0 + 8) * HID + c] =
                    make_float2(acc[mf][nf][2] + b0, acc[mf][nf][3] + b1);
        }
    }
}

// ---------------- launch ----------------------------------------------------
extern "C" void kernel_launch(void* const* d_in, const int* in_sizes, int n_in,
                              void* d_out, int out_size) {
    const float* h    = (const float*)d_in[0];
    const float* frac = (const float*)d_in[1];
    const float* dist = (const float*)d_in[2];
    const int*   ei   = (const int*)d_in[3];
    const float* We   = (const float*)d_in[4];
    const float* be   = (const float*)d_in[5];
    const float* Wq   = (const float*)d_in[6];
    const float* bq   = (const float*)d_in[7];
    const float* Wk   = (const float*)d_in[8];
    const float* bk   = (const float*)d_in[9];
    const float* Wv   = (const float*)d_in[10];
    const float* bv   = (const float*)d_in[11];
    const float* Wo   = (const float*)d_in[12];
    const float* bo   = (const float*)d_in[13];
    const float* Wg1  = (const float*)d_in[14];
    const float* bg1  = (const float*)d_in[15];
    const float* Wg2  = (const float*)d_in[16];
    const float* bg2  = (const float*)d_in[17];

    int n = in_sizes[0] / HID;
    int E = in_sizes[2];
    float* out = (float*)d_out;

    zero_kernel<<<(n * HID + 1023) / 1024, 1024>>>(n);

    dim3 gA((n + 127) / 128, 3);
    qkv_gemm<<<gA, 256>>>(h, frac, We, be, Wq, bq, Wk, bk, Wv, bv, n);

    int eblocks = (E + 7) / 8;
    edge_fused<<<eblocks, 256>>>(ei, dist, Wg1, bg1, Wg2, bg2, E);

    out_gemm<<<(n + 127) / 128, 256>>>(Wo, bo, out, n);
}